// round 15
// baseline (speedup 1.0000x reference)
#include <cuda_runtime.h>
#include <cstdint>

#define NT 60
#define ND 36
#define NL 10
#define NS 9
#define NO 8
#define TPB 128          // 64 consumer threads + 64 producer threads
#define NBJ 16384

typedef unsigned long long u64;

__device__ __forceinline__ float ex2(float x) {
    float r; asm("ex2.approx.ftz.f32 %0, %1;" : "=f"(r) : "f"(x)); return r;
}
__device__ __forceinline__ float frcp(float x) {
    float r; asm("rcp.approx.ftz.f32 %0, %1;" : "=f"(r) : "f"(x)); return r;
}
__device__ __forceinline__ void ffma2(u64& d, u64 a, u64 b) {
    asm("fma.rn.f32x2 %0, %1, %2, %0;" : "+l"(d) : "l"(a), "l"(b));
}
__device__ __forceinline__ u64 pack2(float v) {
    u64 r; asm("mov.b64 %0, {%1, %1};" : "=l"(r) : "f"(v)); return r;
}
__device__ __forceinline__ float2 unpack2(u64 v) {
    float2 f; asm("mov.b64 {%0, %1}, %2;" : "=f"(f.x), "=f"(f.y) : "l"(v)); return f;
}
__device__ __forceinline__ uint32_t smem_u32(const void* p) {
    return (uint32_t)__cvta_generic_to_shared(p);
}
__device__ __forceinline__ void cpasync16(uint32_t dst, const float* src) {
    asm volatile("cp.async.cg.shared.global [%0], [%1], 16;" :: "r"(dst), "l"(src));
}
__device__ __forceinline__ void cpcommit() {
    asm volatile("cp.async.commit_group;" ::: "memory");
}
template<int N> __device__ __forceinline__ void cpwait() {
    asm volatile("cp.async.wait_group %0;" :: "n"(N) : "memory");
}
__device__ __forceinline__ void sts2u64(uint32_t addr, u64 a, u64 b) {
    asm volatile("st.shared.v2.u64 [%0], {%1, %2};" :: "r"(addr), "l"(a), "l"(b) : "memory");
}

// Fused producer/consumer kernel.
//   consumers (tid 0..63): GRU/ODE scan + fused MLP for trajectory g=tid
//   producers (tid 64..127): x-part gate GEMM for trajectory g=tid-64, one
//     row per step into a 2-stage smem ring, 1 step ahead of the consumers.
// Ring row layout (32 floats): [au0-9*L2E | ar0-9*L2E | an0-9 | pad2]
__global__ __launch_bounds__(TPB) void dgm2_fused(
    const float* __restrict__ data,
    const float* __restrict__ ts,
    const float* __restrict__ stat,
    const float* __restrict__ gWu, const float* __restrict__ gbu,
    const float* __restrict__ gWr, const float* __restrict__ gbr,
    const float* __restrict__ gWn, const float* __restrict__ gbn,
    const float* __restrict__ gWo, const float* __restrict__ gbo,
    const float* __restrict__ gWm, const float* __restrict__ gbm,
    float* __restrict__ out)
{
    __shared__ __align__(16) float WA[ND][32];     // producer: [k][u(10) r(10) n(10) pad2]
    __shared__ __align__(16) float biasA[32];
    __shared__ __align__(16) float WuS[NL][12];    // consumer yo-part rows, xL2E
    __shared__ __align__(16) float WrS[NL][12];    // xL2E
    __shared__ __align__(16) float WnS[NL][12];    // candidate rows
    __shared__ __align__(16) float WoS[NL][12];    // x2*L2E
    __shared__ __align__(16) float boS[12];        // x2*L2E
    __shared__ float bmS[NO];
    __shared__ float dtsS[NT];
    __shared__ __align__(16) u64 ring[2][8][64][2];   // 16 KB pre-act ring
    __shared__ __align__(16) float xs[2][64 * ND];    // 18 KB producer x staging

    const int tid = threadIdx.x;
    const float L2E = 1.4426950408889634f;

    // ---- stage weights ----
    for (int i = tid; i < ND * NL; i += TPB) {
        int k = i / NL, j = i - k * NL;
        WA[k][j]      = gWu[(NL + k) * NL + j] * L2E;
        WA[k][10 + j] = gWr[(NL + k) * NL + j] * L2E;
        WA[k][20 + j] = gWn[(NL + k) * NL + j];
    }
    if (tid < NL) {
        biasA[tid]      = gbu[tid] * L2E;
        biasA[10 + tid] = gbr[tid] * L2E;
        biasA[20 + tid] = gbn[tid];
    }
    if (tid < 2) biasA[30 + tid] = 0.f;
    for (int i = tid; i < NL * NL; i += TPB) {
        int r = i / NL, c = i - r * NL;
        WuS[r][c] = gWu[i] * L2E;
        WrS[r][c] = gWr[i] * L2E;
        WnS[r][c] = gWn[i];
        WoS[r][c] = gWo[i] * (2.f * L2E);
    }
    if (tid < NL) boS[tid] = gbo[tid] * (2.f * L2E);
    if (tid < NO) bmS[tid] = gbm[tid];
    for (int i = tid; i < NT; i += TPB)
        dtsS[i] = (i == 0) ? 0.01f : (ts[i] - ts[i - 1]);
    __syncthreads();

    const int g = tid & 63;
    const bool is_prod = (tid >= 64);
    const int b = blockIdx.x * 64 + g;

    // producer state
    const float* xg = data + (size_t)b * NT * ND;
    const uint32_t xsb[2] = { smem_u32(&xs[0][g * ND]), smem_u32(&xs[1][g * ND]) };
    const u64* bpA = (const u64*)biasA;

    // produce one pre-act row from xs[buf] into ring[rb]
    auto produce_row = [&](int buf, int rb) {
        const float4* xr4 = (const float4*)&xs[buf][g * ND];
        float x[ND];
#pragma unroll
        for (int i = 0; i < 9; i++) {
            float4 v = xr4[i];
            x[4 * i] = v.x; x[4 * i + 1] = v.y; x[4 * i + 2] = v.z; x[4 * i + 3] = v.w;
        }
        u64 acc[15];
#pragma unroll
        for (int p = 0; p < 15; p++) acc[p] = bpA[p];
#pragma unroll 6
        for (int k = 0; k < ND; k++) {
            u64 xp = pack2(x[k]);
            const ulonglong2* w2 = (const ulonglong2*)WA[k];
            ulonglong2 wa = w2[0], wb = w2[1], wc = w2[2];
            ulonglong2 wd = w2[3], we_ = w2[4], wf = w2[5], wg_ = w2[6];
            u64 w14 = ((const u64*)WA[k])[14];
            ffma2(acc[0],  xp, wa.x);  ffma2(acc[1],  xp, wa.y);
            ffma2(acc[2],  xp, wb.x);  ffma2(acc[3],  xp, wb.y);
            ffma2(acc[4],  xp, wc.x);  ffma2(acc[5],  xp, wc.y);
            ffma2(acc[6],  xp, wd.x);  ffma2(acc[7],  xp, wd.y);
            ffma2(acc[8],  xp, we_.x); ffma2(acc[9],  xp, we_.y);
            ffma2(acc[10], xp, wf.x);  ffma2(acc[11], xp, wf.y);
            ffma2(acc[12], xp, wg_.x); ffma2(acc[13], xp, wg_.y);
            ffma2(acc[14], xp, w14);
        }
        uint32_t rbase = smem_u32(&ring[rb][0][g][0]);
#pragma unroll
        for (int c = 0; c < 7; c++)
            sts2u64(rbase + c * 1024, acc[2 * c], acc[2 * c + 1]);
        sts2u64(rbase + 7 * 1024, acc[14], 0ull);
    };

    // ---- prologue: producer loads x0,x1 and fills ring stage 0 with row 0 ----
    if (is_prod) {
#pragma unroll
        for (int i = 0; i < 9; i++) cpasync16(xsb[0] + 16 * i, xg + 4 * i);
        cpcommit();
#pragma unroll
        for (int i = 0; i < 9; i++) cpasync16(xsb[1] + 16 * i, xg + ND + 4 * i);
        cpcommit();
        cpwait<1>();          // x0 ready
        produce_row(0, 0);    // row 0 -> ring[0]
    }
    __syncthreads();

    // consumer state
    float y[NL];
    u64 ynp[NL];
    u64 acc2[4];
#pragma unroll
    for (int j = 0; j < NL; j++) { y[j] = 0.f; ynp[j] = 0ull; }
#pragma unroll
    for (int o = 0; o < 4; o++) acc2[o] = 0ull;
    const u64* bop = (const u64*)boS;

#pragma unroll 1
    for (int t = 0; t < NT; t++) {
        if (!is_prod) {
            // ================= CONSUMER: scan step t =================
            const float dt = dtsS[t];
            const float dt2 = 2.f * dt;

            // ODE Euler
            u64 og2[5];
#pragma unroll
            for (int p = 0; p < 5; p++) og2[p] = bop[p];
#pragma unroll
            for (int k = 0; k < NL; k++) {
                const ulonglong2* w = (const ulonglong2*)WoS[k];
                ulonglong2 w01 = w[0], w23 = w[1];
                u64 w4 = ((const u64*)WoS[k])[4];
                ffma2(og2[0], ynp[k], w01.x);
                ffma2(og2[1], ynp[k], w01.y);
                ffma2(og2[2], ynp[k], w23.x);
                ffma2(og2[3], ynp[k], w23.y);
                ffma2(og2[4], ynp[k], w4);
            }
            float yo[NL];
#pragma unroll
            for (int p = 0; p < 5; p++) {
                float2 gg = unpack2(og2[p]);
                yo[2 * p]     = (y[2 * p] + dt)     - dt2 * frcp(ex2(gg.x) + 1.f);
                yo[2 * p + 1] = (y[2 * p + 1] + dt) - dt2 * frcp(ex2(gg.y) + 1.f);
            }
            u64 yop[NL];
#pragma unroll
            for (int k = 0; k < NL; k++) yop[k] = pack2(yo[k]);

            // pre-acts from ring
            const int cb = t & 1;
            u64 pv[16];
#pragma unroll
            for (int c = 0; c < 8; c++) {
                ulonglong2 v = *(const ulonglong2*)&ring[cb][c][g][0];
                pv[2 * c] = v.x; pv[2 * c + 1] = v.y;
            }
            u64 au2[5], ar2[5], an2[5];
#pragma unroll
            for (int p = 0; p < 5; p++) {
                au2[p] = pv[p];
                ar2[p] = pv[5 + p];
                an2[p] = pv[10 + p];
            }
            // yo part for update/reset
#pragma unroll
            for (int k = 0; k < NL; k++) {
                const ulonglong2* wu = (const ulonglong2*)WuS[k];
                const ulonglong2* wr = (const ulonglong2*)WrS[k];
                ulonglong2 u01 = wu[0], u23 = wu[1];
                ulonglong2 r01 = wr[0], r23 = wr[1];
                u64 u4 = ((const u64*)WuS[k])[4];
                u64 r4 = ((const u64*)WrS[k])[4];
                ffma2(au2[0], yop[k], u01.x); ffma2(au2[1], yop[k], u01.y);
                ffma2(au2[2], yop[k], u23.x); ffma2(au2[3], yop[k], u23.y);
                ffma2(au2[4], yop[k], u4);
                ffma2(ar2[0], yop[k], r01.x); ffma2(ar2[1], yop[k], r01.y);
                ffma2(ar2[2], yop[k], r23.x); ffma2(ar2[3], yop[k], r23.y);
                ffma2(ar2[4], yop[k], r4);
            }
            // sigmoid (inputs pre-scaled by log2e)
            float u[NL], r[NL];
#pragma unroll
            for (int p = 0; p < 5; p++) {
                float2 a = unpack2(au2[p]);
                float2 rr = unpack2(ar2[p]);
                u[2 * p]     = frcp(1.f + ex2(-a.x));
                u[2 * p + 1] = frcp(1.f + ex2(-a.y));
                r[2 * p]     = frcp(1.f + ex2(-rr.x));
                r[2 * p + 1] = frcp(1.f + ex2(-rr.y));
            }
            // candidate (yo*r part)
#pragma unroll
            for (int k = 0; k < NL; k++) {
                u64 cp = pack2(yo[k] * r[k]);
                const ulonglong2* wn = (const ulonglong2*)WnS[k];
                ulonglong2 n01 = wn[0], n23 = wn[1];
                u64 n4 = ((const u64*)WnS[k])[4];
                ffma2(an2[0], cp, n01.x); ffma2(an2[1], cp, n01.y);
                ffma2(an2[2], cp, n23.x); ffma2(an2[3], cp, n23.y);
                ffma2(an2[4], cp, n4);
            }
            float yn[NL];
#pragma unroll
            for (int p = 0; p < 5; p++) {
                float2 a = unpack2(an2[p]);
                yn[2 * p]     = a.x + u[2 * p]     * (yo[2 * p]     - a.x);
                yn[2 * p + 1] = a.y + u[2 * p + 1] * (yo[2 * p + 1] - a.y);
            }
#pragma unroll
            for (int k = 0; k < NL; k++) ynp[k] = pack2(yn[k]);

            // fused MLP accumulation (Wm rows via uniform LDG, L1-resident)
            const float* wmrow = gWm + (size_t)t * NL * NO;
#pragma unroll
            for (int l = 0; l < NL; l++) {
                const ulonglong2* wm = (const ulonglong2*)(wmrow + l * NO);
                ulonglong2 w01 = wm[0], w23 = wm[1];
                ffma2(acc2[0], ynp[l], w01.x);
                ffma2(acc2[1], ynp[l], w01.y);
                ffma2(acc2[2], ynp[l], w23.x);
                ffma2(acc2[3], ynp[l], w23.y);
            }
#pragma unroll
            for (int j = 0; j < NL; j++) y[j] = yn[j];
        } else {
            // ================= PRODUCER: row t+1 =================
            const int tt = t + 1;
            if (tt < NT) {
                if (tt + 1 < NT) {
#pragma unroll
                    for (int i = 0; i < 9; i++)
                        cpasync16(xsb[(tt + 1) & 1] + 16 * i, xg + (size_t)(tt + 1) * ND + 4 * i);
                    cpcommit();
                    cpwait<1>();      // x[tt] ready (only x[tt+1] may be pending)
                } else {
                    cpwait<0>();
                }
                produce_row(tt & 1, tt & 1);
            }
        }
        __syncthreads();
    }

    // ---- consumer epilogue: static part + bias + store ----
    if (!is_prod) {
        const float* sp = stat + (size_t)b * NS;
#pragma unroll
        for (int s = 0; s < NS; s++) {
            u64 sv = pack2(sp[s]);
            const ulonglong2* wm = (const ulonglong2*)(gWm + (size_t)(NT * NL + s) * NO);
            ulonglong2 w01 = wm[0], w23 = wm[1];
            ffma2(acc2[0], sv, w01.x);
            ffma2(acc2[1], sv, w01.y);
            ffma2(acc2[2], sv, w23.x);
            ffma2(acc2[3], sv, w23.y);
        }
        float2 a0 = unpack2(acc2[0]), a1 = unpack2(acc2[1]);
        float2 a2 = unpack2(acc2[2]), a3 = unpack2(acc2[3]);
        float4 o0, o1;
        o0.x = a0.x + bmS[0]; o0.y = a0.y + bmS[1];
        o0.z = a1.x + bmS[2]; o0.w = a1.y + bmS[3];
        o1.x = a2.x + bmS[4]; o1.y = a2.y + bmS[5];
        o1.z = a3.x + bmS[6]; o1.w = a3.y + bmS[7];
        float4* op = reinterpret_cast<float4*>(out + (size_t)b * NO);
        op[0] = o0;
        op[1] = o1;
    }
}

extern "C" void kernel_launch(void* const* d_in, const int* in_sizes, int n_in,
                              void* d_out, int out_size) {
    // single fused kernel: 256 blocks x (64 consumer + 64 producer) threads
    dgm2_fused<<<NBJ / 64, TPB>>>(
        (const float*)d_in[0],                            // data
        (const float*)d_in[1],                            // time_steps
        (const float*)d_in[2],                            // static_data
        (const float*)d_in[3],  (const float*)d_in[4],    // W_update, b_update
        (const float*)d_in[5],  (const float*)d_in[6],    // W_reset,  b_reset
        (const float*)d_in[7],  (const float*)d_in[8],    // W_new,    b_new
        // d_in[9], d_in[10] (W_emit, b_emit) are dead code
        (const float*)d_in[11], (const float*)d_in[12],   // W_ode, b_ode
        (const float*)d_in[13], (const float*)d_in[14],   // W_mlp, b_mlp
        (float*)d_out);
}

// round 16
// speedup vs baseline: 1.5683x; 1.5683x over previous
#include <cuda_runtime.h>
#include <cstdint>

#define NT 60
#define ND 36
#define NL 10
#define NS 9
#define NO 8
#define MIN_ (NT*NL + NS) // 609
#define NBJ 16384
#define ROWS ((size_t)NBJ * NT)   // 983040
#define NREG 256                  // B regions (64 trajectories each)
#define CH 15                     // time chunks
#define CS 4                      // steps per chunk  (CH*CS = NT)

typedef unsigned long long u64;

// scratch: per (b,t) row of 32 floats: au[10]*L2E, ar[10]*L2E, an[10], pad[2]
__device__ __align__(128) float g_pre[ROWS * 32];
__device__ int g_flags[NREG * CH];

__device__ __forceinline__ float ex2(float x) {
    float r; asm("ex2.approx.ftz.f32 %0, %1;" : "=f"(r) : "f"(x)); return r;
}
__device__ __forceinline__ float frcp(float x) {
    float r; asm("rcp.approx.ftz.f32 %0, %1;" : "=f"(r) : "f"(x)); return r;
}
__device__ __forceinline__ void ffma2(u64& d, u64 a, u64 b) {
    asm("fma.rn.f32x2 %0, %1, %2, %0;" : "+l"(d) : "l"(a), "l"(b));
}
__device__ __forceinline__ u64 pack2(float v) {
    u64 r; asm("mov.b64 %0, {%1, %1};" : "=l"(r) : "f"(v)); return r;
}
__device__ __forceinline__ float2 unpack2(u64 v) {
    float2 f; asm("mov.b64 {%0, %1}, %2;" : "=f"(f.x), "=f"(f.y) : "l"(v)); return f;
}
__device__ __forceinline__ uint32_t smem_u32(const void* p) {
    return (uint32_t)__cvta_generic_to_shared(p);
}
__device__ __forceinline__ void cpasync16(uint32_t dst, const float* src) {
    asm volatile("cp.async.cg.shared.global [%0], [%1], 16;" :: "r"(dst), "l"(src));
}
__device__ __forceinline__ void cpcommit() {
    asm volatile("cp.async.commit_group;" ::: "memory");
}
template<int N> __device__ __forceinline__ void cpwait() {
    asm volatile("cp.async.wait_group %0;" :: "n"(N) : "memory");
}

// ---- shared-memory overlays ----
struct __align__(16) AS {                 // producer (A) role: 42.7 KB
    float W[ND][32];                      // [k][u(10) r(10) n(10) pad2]
    float bias[32];
    float buf[256 * 37];                  // in: 256 rows pad-37; out: pad-33
};
struct __align__(16) SWB {
    float Wu[NL][12];                     // yo-part rows, xL2E
    float Wr[NL][12];                     // xL2E
    float Wn[NL][12];                     // candidate rows
    float Wo[NL][12];                     // x2*L2E
    float Wm[MIN_][NO];
    float bo[12];                         // x2*L2E
    float bm[NO];
    float dts[NT];
};
struct __align__(16) BS {                 // consumer (B) role: 38.1 KB
    SWB sw;
    u64 ring[2][8][64][2];
};

__global__ void init_flags_kernel() {
    int i = blockIdx.x * 256 + threadIdx.x;
    if (i < NREG * CH) g_flags[i] = 0;
}

__global__ __launch_bounds__(128) void dgm2_pipe(
    const float* __restrict__ data,
    const float* __restrict__ ts,
    const float* __restrict__ stat,
    const float* __restrict__ gWu, const float* __restrict__ gbu,
    const float* __restrict__ gWr, const float* __restrict__ gbr,
    const float* __restrict__ gWn, const float* __restrict__ gbn,
    const float* __restrict__ gWo, const float* __restrict__ gbo,
    const float* __restrict__ gWm, const float* __restrict__ gbm,
    float* __restrict__ out)
{
    __shared__ __align__(16) char arena[43776];
    const int tid = threadIdx.x;
    const float L2E = 1.4426950408889634f;

    if (blockIdx.x >= NREG) {
        // ===================== A role: pre-act tile (64 traj x 4 steps) ====
        AS& A = *reinterpret_cast<AS*>(arena);
        const int a = blockIdx.x - NREG;
        const int c = a / NREG;           // chunk (chunk-major: all regions' chunk 0 first)
        const int i = a % NREG;           // region

        for (int q = tid; q < ND * NL; q += 128) {
            int k = q / NL, j = q - k * NL;
            A.W[k][j]      = gWu[(NL + k) * NL + j] * L2E;
            A.W[k][10 + j] = gWr[(NL + k) * NL + j] * L2E;
            A.W[k][20 + j] = gWn[(NL + k) * NL + j];
        }
        for (int q = tid; q < ND * 2; q += 128) A.W[q / 2][30 + (q & 1)] = 0.f;
        if (tid < NL) {
            A.bias[tid]      = gbu[tid] * L2E;
            A.bias[10 + tid] = gbr[tid] * L2E;
            A.bias[20 + tid] = gbn[tid];
        }
        if (tid < 2) A.bias[30 + tid] = 0.f;

        // ---- load input tile: 64 trajs x 4 steps x 36 floats -> pad-37 rows ----
        // row = lt*4 + tt
#pragma unroll
        for (int j = 0; j < 18; j++) {
            int f4 = tid + 128 * j;       // 0..2303
            int lt = f4 / 36;
            int r4 = f4 - lt * 36;
            int tt = r4 / 9;
            int d4 = r4 - tt * 9;
            const float4 v = *reinterpret_cast<const float4*>(
                data + (((size_t)(64 * i + lt)) * NT + (size_t)(CS * c + tt)) * ND + 4 * d4);
            float* drow = A.buf + (lt * 4 + tt) * 37 + 4 * d4;
            drow[0] = v.x; drow[1] = v.y; drow[2] = v.z; drow[3] = v.w;
        }
        __syncthreads();

        // ---- compute: 2 rows/thread (rows tid, tid+128) ----
        const float* x0 = A.buf + tid * 37;
        const float* x1 = A.buf + (tid + 128) * 37;
        u64 a0[15], a1[15];
        const u64* bp = (const u64*)A.bias;
#pragma unroll
        for (int p = 0; p < 15; p++) { a0[p] = bp[p]; a1[p] = bp[p]; }
#pragma unroll 6
        for (int k = 0; k < ND; k++) {
            u64 xp0 = pack2(x0[k]);
            u64 xp1 = pack2(x1[k]);
            const ulonglong2* w2 = (const ulonglong2*)A.W[k];
            ulonglong2 wa = w2[0], wb = w2[1], wc = w2[2];
            ulonglong2 wd = w2[3], we_ = w2[4], wf = w2[5], wg = w2[6];
            u64 w14 = ((const u64*)A.W[k])[14];
            ffma2(a0[0],  xp0, wa.x);  ffma2(a1[0],  xp1, wa.x);
            ffma2(a0[1],  xp0, wa.y);  ffma2(a1[1],  xp1, wa.y);
            ffma2(a0[2],  xp0, wb.x);  ffma2(a1[2],  xp1, wb.x);
            ffma2(a0[3],  xp0, wb.y);  ffma2(a1[3],  xp1, wb.y);
            ffma2(a0[4],  xp0, wc.x);  ffma2(a1[4],  xp1, wc.x);
            ffma2(a0[5],  xp0, wc.y);  ffma2(a1[5],  xp1, wc.y);
            ffma2(a0[6],  xp0, wd.x);  ffma2(a1[6],  xp1, wd.x);
            ffma2(a0[7],  xp0, wd.y);  ffma2(a1[7],  xp1, wd.y);
            ffma2(a0[8],  xp0, we_.x); ffma2(a1[8],  xp1, we_.x);
            ffma2(a0[9],  xp0, we_.y); ffma2(a1[9],  xp1, we_.y);
            ffma2(a0[10], xp0, wf.x);  ffma2(a1[10], xp1, wf.x);
            ffma2(a0[11], xp0, wf.y);  ffma2(a1[11], xp1, wf.y);
            ffma2(a0[12], xp0, wg.x);  ffma2(a1[12], xp1, wg.x);
            ffma2(a0[13], xp0, wg.y);  ffma2(a1[13], xp1, wg.y);
            ffma2(a0[14], xp0, w14);   ffma2(a1[14], xp1, w14);
        }
        __syncthreads();   // input reads done; reuse buf as pad-33 out staging

        {
            float* o0 = A.buf + tid * 33;
            float* o1 = A.buf + (tid + 128) * 33;
#pragma unroll
            for (int p = 0; p < 15; p++) {
                float2 f0 = unpack2(a0[p]);
                float2 f1 = unpack2(a1[p]);
                o0[2 * p] = f0.x; o0[2 * p + 1] = f0.y;
                o1[2 * p] = f1.x; o1[2 * p + 1] = f1.y;
            }
            o0[30] = 0.f; o0[31] = 0.f;
            o1[30] = 0.f; o1[31] = 0.f;
        }
        __syncthreads();

        // ---- store tile (coalesced within 512B traj-chunks) ----
#pragma unroll
        for (int j = 0; j < 16; j++) {
            int o4 = tid + 128 * j;       // 0..2047
            int row = o4 >> 3, q = o4 & 7;
            const float* s = A.buf + row * 33 + 4 * q;
            int lt = row >> 2, tt = row & 3;
            float4* dst = reinterpret_cast<float4*>(
                g_pre + (((size_t)(64 * i + lt)) * NT + (size_t)(CS * c + tt)) * 32) + q;
            *dst = make_float4(s[0], s[1], s[2], s[3]);
        }
        __threadfence();
        __syncthreads();
        if (tid == 0) atomicExch(&g_flags[i * CH + c], 1);
        return;
    }

    // ===================== B role: persistent recurrent scan ================
    BS& B = *reinterpret_cast<BS*>(arena);
    SWB& sw = B.sw;

    for (int q = tid; q < NL * NL; q += 128) {
        int r = q / NL, cc = q - r * NL;
        sw.Wu[r][cc] = gWu[q] * L2E;
        sw.Wr[r][cc] = gWr[q] * L2E;
        sw.Wn[r][cc] = gWn[q];
        sw.Wo[r][cc] = gWo[q] * (2.f * L2E);
    }
    for (int q = tid; q < MIN_ * NO; q += 128) (&sw.Wm[0][0])[q] = gWm[q];
    if (tid < 12) sw.bo[tid] = 0.f;
    __syncthreads();
    if (tid < NL) sw.bo[tid] = gbo[tid] * (2.f * L2E);
    if (tid < NO) sw.bm[tid] = gbm[tid];
    for (int q = tid; q < NT; q += 128)
        sw.dts[q] = (q == 0) ? 0.01f : (ts[q] - ts[q - 1]);
    __syncthreads();
    if (tid >= 64) return;                // only 2 warps scan (no more block syncs)

    const int g = tid;
    const int b = blockIdx.x * 64 + g;
    const float* pg = g_pre + (size_t)b * NT * 32;
    const int* myflags = &g_flags[blockIdx.x * CH];

    float y[NL];
    u64 ynp[NL];
    u64 acc2[4];
#pragma unroll
    for (int j = 0; j < NL; j++) { y[j] = 0.f; ynp[j] = 0ull; }
#pragma unroll
    for (int o = 0; o < 4; o++) acc2[o] = 0ull;
    const u64* bop = (const u64*)sw.bo;

#pragma unroll 1
    for (int c2 = 0; c2 < CH; c2++) {
        // wait for this region's chunk to be produced
        while (*(volatile const int*)&myflags[c2] == 0) __nanosleep(64);
        __threadfence();   // acquire

        // load first row of chunk (parity of 4*c2 is 0)
        {
            const float* src = pg + (size_t)(CS * c2) * 32;
#pragma unroll
            for (int ch = 0; ch < 8; ch++)
                cpasync16(smem_u32(&B.ring[0][ch][g][0]), src + 4 * ch);
            cpcommit();
        }

#pragma unroll 1
        for (int tt = 0; tt < CS; tt++) {
            const int t = CS * c2 + tt;
            if (tt < CS - 1) {
                const int nb = (t + 1) & 1;
                const float* src = pg + (size_t)(t + 1) * 32;
#pragma unroll
                for (int ch = 0; ch < 8; ch++)
                    cpasync16(smem_u32(&B.ring[nb][ch][g][0]), src + 4 * ch);
                cpcommit();
                cpwait<1>();
            } else {
                cpwait<0>();
            }
            const float dt = sw.dts[t];
            const float dt2 = 2.f * dt;

            // ---- ODE Euler ----
            u64 og2[5];
#pragma unroll
            for (int p = 0; p < 5; p++) og2[p] = bop[p];
#pragma unroll
            for (int k = 0; k < NL; k++) {
                const ulonglong2* w = (const ulonglong2*)sw.Wo[k];
                ulonglong2 w01 = w[0], w23 = w[1];
                u64 w4 = ((const u64*)sw.Wo[k])[4];
                ffma2(og2[0], ynp[k], w01.x);
                ffma2(og2[1], ynp[k], w01.y);
                ffma2(og2[2], ynp[k], w23.x);
                ffma2(og2[3], ynp[k], w23.y);
                ffma2(og2[4], ynp[k], w4);
            }
            float yo[NL];
#pragma unroll
            for (int p = 0; p < 5; p++) {
                float2 gg = unpack2(og2[p]);
                yo[2 * p]     = (y[2 * p] + dt)     - dt2 * frcp(ex2(gg.x) + 1.f);
                yo[2 * p + 1] = (y[2 * p + 1] + dt) - dt2 * frcp(ex2(gg.y) + 1.f);
            }
            u64 yop[NL];
#pragma unroll
            for (int k = 0; k < NL; k++) yop[k] = pack2(yo[k]);

            // ---- gate accumulators from streamed pre-activations ----
            u64 pv[16];
            const int cb = t & 1;
#pragma unroll
            for (int ch = 0; ch < 8; ch++) {
                ulonglong2 v = *(const ulonglong2*)&B.ring[cb][ch][g][0];
                pv[2 * ch] = v.x; pv[2 * ch + 1] = v.y;
            }
            u64 au2[5], ar2[5], an2[5];
#pragma unroll
            for (int p = 0; p < 5; p++) {
                au2[p] = pv[p];
                ar2[p] = pv[5 + p];
                an2[p] = pv[10 + p];
            }
            // yo part for update/reset
#pragma unroll
            for (int k = 0; k < NL; k++) {
                const ulonglong2* wu = (const ulonglong2*)sw.Wu[k];
                const ulonglong2* wr = (const ulonglong2*)sw.Wr[k];
                ulonglong2 u01 = wu[0], u23 = wu[1];
                ulonglong2 r01 = wr[0], r23 = wr[1];
                u64 u4 = ((const u64*)sw.Wu[k])[4];
                u64 r4 = ((const u64*)sw.Wr[k])[4];
                ffma2(au2[0], yop[k], u01.x); ffma2(au2[1], yop[k], u01.y);
                ffma2(au2[2], yop[k], u23.x); ffma2(au2[3], yop[k], u23.y);
                ffma2(au2[4], yop[k], u4);
                ffma2(ar2[0], yop[k], r01.x); ffma2(ar2[1], yop[k], r01.y);
                ffma2(ar2[2], yop[k], r23.x); ffma2(ar2[3], yop[k], r23.y);
                ffma2(ar2[4], yop[k], r4);
            }
            // sigmoid (inputs pre-scaled by log2e)
            float u[NL], r[NL];
#pragma unroll
            for (int p = 0; p < 5; p++) {
                float2 a = unpack2(au2[p]);
                float2 rr = unpack2(ar2[p]);
                u[2 * p]     = frcp(1.f + ex2(-a.x));
                u[2 * p + 1] = frcp(1.f + ex2(-a.y));
                r[2 * p]     = frcp(1.f + ex2(-rr.x));
                r[2 * p + 1] = frcp(1.f + ex2(-rr.y));
            }
            // candidate (yo*r part)
#pragma unroll
            for (int k = 0; k < NL; k++) {
                u64 cp = pack2(yo[k] * r[k]);
                const ulonglong2* wn = (const ulonglong2*)sw.Wn[k];
                ulonglong2 n01 = wn[0], n23 = wn[1];
                u64 n4 = ((const u64*)sw.Wn[k])[4];
                ffma2(an2[0], cp, n01.x); ffma2(an2[1], cp, n01.y);
                ffma2(an2[2], cp, n23.x); ffma2(an2[3], cp, n23.y);
                ffma2(an2[4], cp, n4);
            }
            float yn[NL];
#pragma unroll
            for (int p = 0; p < 5; p++) {
                float2 a = unpack2(an2[p]);
                yn[2 * p]     = a.x + u[2 * p]     * (yo[2 * p]     - a.x);
                yn[2 * p + 1] = a.y + u[2 * p + 1] * (yo[2 * p + 1] - a.y);
            }
#pragma unroll
            for (int k = 0; k < NL; k++) ynp[k] = pack2(yn[k]);

            // ---- fused MLP accumulation ----
            const float* wmrow = &sw.Wm[t * NL][0];
#pragma unroll
            for (int l = 0; l < NL; l++) {
                const ulonglong2* wm = (const ulonglong2*)(wmrow + l * NO);
                ulonglong2 w01 = wm[0], w23 = wm[1];
                ffma2(acc2[0], ynp[l], w01.x);
                ffma2(acc2[1], ynp[l], w01.y);
                ffma2(acc2[2], ynp[l], w23.x);
                ffma2(acc2[3], ynp[l], w23.y);
            }
#pragma unroll
            for (int j = 0; j < NL; j++) y[j] = yn[j];
        }
    }

    // ---- static part + bias ----
    const float* sp = stat + (size_t)b * NS;
#pragma unroll
    for (int s = 0; s < NS; s++) {
        u64 sv = pack2(sp[s]);
        const ulonglong2* wm = (const ulonglong2*)&sw.Wm[NT * NL + s][0];
        ulonglong2 w01 = wm[0], w23 = wm[1];
        ffma2(acc2[0], sv, w01.x);
        ffma2(acc2[1], sv, w01.y);
        ffma2(acc2[2], sv, w23.x);
        ffma2(acc2[3], sv, w23.y);
    }
    float2 a0 = unpack2(acc2[0]), a1 = unpack2(acc2[1]);
    float2 a2 = unpack2(acc2[2]), a3 = unpack2(acc2[3]);
    float4 o0, o1;
    o0.x = a0.x + sw.bm[0]; o0.y = a0.y + sw.bm[1];
    o0.z = a1.x + sw.bm[2]; o0.w = a1.y + sw.bm[3];
    o1.x = a2.x + sw.bm[4]; o1.y = a2.y + sw.bm[5];
    o1.z = a3.x + sw.bm[6]; o1.w = a3.y + sw.bm[7];
    float4* op = reinterpret_cast<float4*>(out + (size_t)b * NO);
    op[0] = o0;
    op[1] = o1;
}

extern "C" void kernel_launch(void* const* d_in, const int* in_sizes, int n_in,
                              void* d_out, int out_size) {
    init_flags_kernel<<<CH, 256>>>();
    // blocks 0..255: persistent consumers (B); blocks 256..4095: producers (A),
    // chunk-major so every region's chunk 0 is produced first.
    dgm2_pipe<<<NREG + NREG * CH, 128>>>(
        (const float*)d_in[0],                            // data
        (const float*)d_in[1],                            // time_steps
        (const float*)d_in[2],                            // static_data
        (const float*)d_in[3],  (const float*)d_in[4],    // W_update, b_update
        (const float*)d_in[5],  (const float*)d_in[6],    // W_reset,  b_reset
        (const float*)d_in[7],  (const float*)d_in[8],    // W_new,    b_new
        // d_in[9], d_in[10] (W_emit, b_emit) are dead code
        (const float*)d_in[11], (const float*)d_in[12],   // W_ode, b_ode
        (const float*)d_in[13], (const float*)d_in[14],   // W_mlp, b_mlp
        (float*)d_out);
}